// round 14
// baseline (speedup 1.0000x reference)
#include <cuda_runtime.h>
#include <math.h>

#define NB 32
#define NNODE 2048
#define TT 96
#define KE 20
#define DNODE 40
#define DH 64
#define DG 16
#define NROWS (NB*NNODE)

// ---------------- scratch ----------
__device__ float g_nv1[NNODE*DNODE];
__device__ float g_nv2[NNODE*DNODE];
__device__ float g_Wd[TT*TT];
__device__ float g_adj[(size_t)NNODE*NNODE];
__device__ int   g_cols[NNODE*KE];
__device__ float g_maskv[NNODE*KE];
__device__ int   g_cnt[NNODE];
__device__ int   g_cnt2[NNODE];
__device__ int   g_ptr[NNODE+1];
__device__ int   g_rsrc[NNODE*KE];
__device__ float g_m[(size_t)NROWS*TT];
__device__ float g_xx[(size_t)NROWS*TT];
__device__ float g_skipA[(size_t)NROWS*TT];
__device__ float g_s1[NROWS];
__device__ float g_h[(size_t)NROWS*DG];
__device__ float g_gate[(size_t)NROWS*DG];
__device__ float g_xgg[(size_t)NROWS*DG];
__device__ float g_xx2[(size_t)NROWS*TT];
__device__ float g_part[2048];
__device__ float g_mu[NB];
__device__ float g_rstd[NB];

// ---------------- XLA EmitTanh f32: rational, clamp +-7.99881172180175781 ----
__device__ __forceinline__ float xtanh(float x){
  const float kClamp = 7.99881172180175781f;
  float xc = fminf(fmaxf(x, -kClamp), kClamp);
  float x2 = xc*xc;
  float p = fmaf(x2, -2.76076847742355e-16f, 2.00018790482477e-13f);
  p = fmaf(x2, p, -8.60467152213735e-11f);
  p = fmaf(x2, p,  5.12229709037114e-08f);
  p = fmaf(x2, p,  1.48572235717979e-05f);
  p = fmaf(x2, p,  6.37261928875436e-04f);
  p = fmaf(x2, p,  4.89352455891786e-03f);
  p = xc * p;
  float q = fmaf(x2, 1.19825839466702e-06f, 1.18534705686654e-04f);
  q = fmaf(x2, q, 2.26843463243900e-03f);
  q = fmaf(x2, q, 4.89352518554385e-03f);
  return (fabsf(x) < 0.0004f) ? x : (p/q);
}

// ---------------- graph pre: nv1 | nv2 | Wd | zero-cnt in one launch ----
__global__ void k_graphpre(const float* __restrict__ emb1, const float* __restrict__ emb2,
                           const float* __restrict__ w1, const float* __restrict__ b1,
                           const float* __restrict__ w2, const float* __restrict__ b2,
                           const float* __restrict__ wt, const float* __restrict__ wsm){
  int bx = blockIdx.x;
  if (bx < 640){
    int which = bx >= 320;
    int idx = (which ? bx-320 : bx)*256 + threadIdx.x;
    int i = idx / DNODE, j = idx - i*DNODE;
    const float* e  = (which ? emb2 : emb1) + i*DNODE;
    const float* wr = (which ? w2 : w1) + j*DNODE;
    const float* bb = which ? b2 : b1;
    float s = 0.f;
    #pragma unroll
    for (int k=0;k<DNODE;k++) s = fmaf(e[k], wr[k], s);
    float v = xtanh(3.0f*(s + bb[j]));
    if (which) g_nv2[idx] = v; else g_nv1[idx] = v;
  } else if (bx < 676){
    int i = (bx-640)*256 + threadIdx.x;
    if (i < TT*TT) g_Wd[i] = wt[i] - wsm[i];
  } else {
    int i = (bx-676)*256 + threadIdx.x;
    if (i < NNODE){ g_cnt[i]=0; g_cnt2[i]=0; }
  }
}

// 64x64 tile, 4x4 micro-tile per thread, transposed smem [k][row] pad-65.
__global__ void __launch_bounds__(256) k_adj(){
  __shared__ float sA1[DNODE*65], sA2[DNODE*65], sB1[DNODE*65], sB2[DNODE*65];
  const int tid = threadIdx.x;
  const int i0 = blockIdx.y*64, j0 = blockIdx.x*64;
  for (int idx=tid; idx<64*DNODE; idx+=256){
    int r = idx/DNODE, k = idx - r*DNODE;
    sA1[k*65+r] = g_nv1[(i0+r)*DNODE+k];
    sA2[k*65+r] = g_nv2[(i0+r)*DNODE+k];
    sB1[k*65+r] = g_nv1[(j0+r)*DNODE+k];
    sB2[k*65+r] = g_nv2[(j0+r)*DNODE+k];
  }
  __syncthreads();
  const int tx = tid & 15, ty = tid >> 4;
  float p[16], q[16];
  #pragma unroll
  for (int i=0;i<16;i++){ p[i]=0.f; q[i]=0.f; }
  #pragma unroll 4
  for (int k=0;k<DNODE;k++){
    float a1[4], a2[4], b1[4], b2[4];
    #pragma unroll
    for (int i=0;i<4;i++){
      a1[i] = sA1[k*65 + ty*4+i];
      a2[i] = sA2[k*65 + ty*4+i];
      b1[i] = sB1[k*65 + tx*4+i];
      b2[i] = sB2[k*65 + tx*4+i];
    }
    #pragma unroll
    for (int i=0;i<4;i++)
      #pragma unroll
      for (int j=0;j<4;j++){
        p[i*4+j] = fmaf(a1[i], b2[j], p[i*4+j]);
        q[i*4+j] = fmaf(a2[i], b1[j], q[i*4+j]);
      }
  }
  #pragma unroll
  for (int i=0;i<4;i++){
    size_t rowo = (size_t)(i0 + ty*4 + i)*NNODE + j0 + tx*4;
    #pragma unroll
    for (int j=0;j<4;j++){
      float t = xtanh(3.0f*(p[i*4+j]-q[i*4+j]));
      g_adj[rowo + j] = fmaxf(t, 0.f);
    }
  }
}

// ---------------- top-k + fused degree count (ties -> lowest index) ----
__global__ void k_topk(){
  __shared__ unsigned long long red[8];
  __shared__ unsigned long long s_win;
  const int row = blockIdx.x, tid = threadIdx.x;
  const float* ar = g_adj + (size_t)row*NNODE;
  unsigned long long key[8];
  #pragma unroll
  for (int j=0;j<8;j++){
    int i = j*256 + tid;
    unsigned int b = __float_as_uint(ar[i]);
    b = (b & 0x80000000u) ? ~b : (b | 0x80000000u);
    key[j] = ((unsigned long long)b<<32) | (unsigned int)(NNODE-1-i);
  }
  for (int k=0;k<KE;k++){
    unsigned long long best = key[0];
    #pragma unroll
    for (int j=1;j<8;j++) best = best > key[j] ? best : key[j];
    #pragma unroll
    for (int o=16;o;o>>=1){
      unsigned long long other = __shfl_xor_sync(0xffffffffu, best, o);
      if (other > best) best = other;
    }
    if ((tid&31)==0) red[tid>>5] = best;
    __syncthreads();
    if (tid==0){
      unsigned long long bb = red[0];
      #pragma unroll
      for (int i=1;i<8;i++) if (red[i] > bb) bb = red[i];
      s_win = bb;
      int idx = NNODE-1-(int)(bb & 0xffffffffull);
      bool pos = ((unsigned int)(bb>>32) > 0x80000000u);
      g_cols[row*KE+k]  = idx;
      g_maskv[row*KE+k] = pos ? 1.f : 0.f;
      if (pos) atomicAdd(&g_cnt[idx], 1);
    }
    __syncthreads();
    int idx = NNODE-1-(int)(s_win & 0xffffffffull);
    if ((idx & 255) == tid) key[idx>>8] = 0ull;
  }
}

// ---------------- scan: 1 block over 2048 counts ----
__global__ void k_scan(){
  __shared__ int sa[NNODE], sb[NNODE];
  const int t = threadIdx.x;    // 1024
  sa[t] = g_cnt[t]; sa[t+1024] = g_cnt[t+1024];
  __syncthreads();
  int *src=sa, *dst=sb;
  for (int off=1; off<NNODE; off<<=1){
    for (int i=t;i<NNODE;i+=1024){
      int v = src[i];
      if (i >= off) v += src[i-off];
      dst[i] = v;
    }
    __syncthreads();
    int* tmp=src; src=dst; dst=tmp;
  }
  if (t==0) g_ptr[0]=0;
  g_ptr[t+1] = src[t];
  g_ptr[t+1024+1] = src[t+1024];
}

// ---------------- fill: parallel ----
__global__ void k_fill(){
  int idx = blockIdx.x*256+threadIdx.x;
  if (idx >= NNODE*KE) return;
  if (g_maskv[idx] > 0.f){
    int n = idx/KE;
    int c = g_cols[idx];
    int s = atomicAdd(&g_cnt2[c], 1);
    g_rsrc[g_ptr[c]+s] = n;
  }
}

// ---------------- decomposition: m = ma1+ma2 ----
__global__ void k_decomp(const float* __restrict__ x){
  __shared__ float sx[4][TT], sst[4][TT];
  int ty = threadIdx.y, t = threadIdx.x;
  size_t r = (size_t)blockIdx.x*4 + ty;
  sx[ty][t] = x[r*TT + t];
  __syncthreads();
  float s = 0.f;
  #pragma unroll
  for (int d=-12; d<=12; d++){
    int j = t+d; j = max(0, min(TT-1, j));
    s += sx[ty][j];
  }
  float ma1 = s / 25.0f;
  sst[ty][t] = sx[ty][t] - ma1;
  __syncthreads();
  s = 0.f;
  #pragma unroll
  for (int d=-12; d<=12; d++){
    int j = t+d; j = max(0, min(TT-1, j));
    s += sst[ty][j];
  }
  g_m[r*TT + t] = ma1 + s / 25.0f;
}

// ---------------- fused GEMM1 (N-split x2): xx = x@Ws^T + m@Wd^T + b; skipA = x@W0^T + b0
__global__ void __launch_bounds__(256) k_gemm1(
    const float* __restrict__ x,  const float* __restrict__ w0, const float* __restrict__ b0,
    const float* __restrict__ ws, const float* __restrict__ bs, const float* __restrict__ bt){
  extern __shared__ float sm[];
  float* sX  = sm;
  float* sM  = sX  + 64*97;
  float* sWs = sM  + 64*97;
  float* sWd = sWs + 48*97;
  float* sW0 = sWd + 48*97;
  const int tid = threadIdx.x;
  const size_t row0 = (size_t)blockIdx.x*64;
  const int c0 = blockIdx.y*48;
  for (int i=tid;i<64*96;i+=256){
    int r=i/96, c=i-r*96;
    size_t g = (row0+r)*96 + c;
    sX[r*97+c] = x[g];
    sM[r*97+c] = g_m[g];
  }
  for (int i=tid;i<48*96;i+=256){
    int r=i/96, c=i-r*96;
    int gi = (c0+r)*96 + c;
    sWs[r*97+c] = ws[gi];
    sWd[r*97+c] = g_Wd[gi];
    sW0[r*97+c] = w0[gi];
  }
  __syncthreads();
  const int cx = tid & 15, ry = tid >> 4;
  const float* A   = sX  + ry*4*97;
  const float* M   = sM  + ry*4*97;
  const float* Wsp = sWs + cx*3*97;
  const float* Wdp = sWd + cx*3*97;
  const float* W0p = sW0 + cx*3*97;
  float aX[12], aS[12];
  #pragma unroll
  for (int i=0;i<12;i++){ aX[i]=0.f; aS[i]=0.f; }
  #pragma unroll 2
  for (int k=0;k<96;k++){
    float xv[4], mv[4];
    #pragma unroll
    for (int j=0;j<4;j++){ xv[j]=A[j*97+k]; mv[j]=M[j*97+k]; }
    #pragma unroll
    for (int i=0;i<3;i++){
      float fws=Wsp[i*97+k], fwd=Wdp[i*97+k], fw0=W0p[i*97+k];
      #pragma unroll
      for (int j=0;j<4;j++){
        aX[j*3+i] = fmaf(xv[j], fws, fmaf(mv[j], fwd, aX[j*3+i]));
        aS[j*3+i] = fmaf(xv[j], fw0, aS[j*3+i]);
      }
    }
  }
  #pragma unroll
  for (int j=0;j<4;j++){
    size_t row = row0 + ry*4 + j;
    #pragma unroll
    for (int i=0;i<3;i++){
      int c = c0 + cx*3 + i;
      size_t g = row*96 + c;
      g_xx[g]    = aX[j*3+i] + bs[c] + bt[c];
      g_skipA[g] = aS[j*3+i] + b0[c];
    }
  }
}

// ---------------- k_xg: xg = xx@lin1^T+b (smem) ; s1 ; h,gate from smem xg ----
__global__ void __launch_bounds__(256) k_xg(
    const float* __restrict__ l1w, const float* __restrict__ l1b,
    const float* __restrict__ s1w, const float* __restrict__ s1b,
    const float* __restrict__ msgw, const float* __restrict__ msgb,
    const float* __restrict__ gatew, const float* __restrict__ gateb){
  extern __shared__ float sm[];
  float* sA = sm;            // 64*97 xx
  float* sW = sA + 64*97;    // 64*97 l1w; later reused as xg tile [64][65]
  __shared__ float sMW[2*DG*DH];
  const int tid = threadIdx.x;
  const size_t row0 = (size_t)blockIdx.x*64;
  for (int i=tid;i<64*96;i+=256){
    int r=i/96, c=i-r*96;
    sA[r*97+c] = g_xx[(row0+r)*96 + c];
    sW[r*97+c] = l1w[i];
  }
  for (int i=tid;i<DG*DH;i+=256){
    sMW[i] = msgw[i];
    sMW[DG*DH + i] = gatew[i];
  }
  __syncthreads();
  const int cx = tid & 15, ry = tid >> 4;
  {
    const float* A = sA + ry*4*97;
    const float* W = sW + cx*4*97;
    float acc[16];
    #pragma unroll
    for (int i=0;i<16;i++) acc[i]=0.f;
    #pragma unroll 2
    for (int k=0;k<96;k++){
      float a[4];
      #pragma unroll
      for (int j=0;j<4;j++) a[j]=A[j*97+k];
      #pragma unroll
      for (int i=0;i<4;i++){
        float w = W[i*97+k];
        #pragma unroll
        for (int j=0;j<4;j++) acc[j*4+i] = fmaf(a[j], w, acc[j*4+i]);
      }
    }
    if (tid < 64){
      float s = 0.f;
      #pragma unroll 4
      for (int k=0;k<96;k++) s = fmaf(sA[tid*97+k], s1w[k], s);
      g_s1[row0+tid] = s + s1b[0];
    }
    __syncthreads();
    #pragma unroll
    for (int j=0;j<4;j++)
      #pragma unroll
      for (int i=0;i<4;i++)
        sW[(ry*4+j)*65 + cx*4+i] = acc[j*4+i] + l1b[cx*4+i];
  }
  __syncthreads();
  const int row = tid >> 2, q = tid & 3;
  float ha[4] = {0,0,0,0}, ga[4] = {0,0,0,0};
  #pragma unroll 4
  for (int k=0;k<DH;k++){
    float xv = sW[row*65+k];
    #pragma unroll
    for (int i=0;i<4;i++){
      ha[i] = fmaf(xv, sMW[(q*4+i)*DH+k], ha[i]);
      ga[i] = fmaf(xv, sMW[DG*DH + (q*4+i)*DH+k], ga[i]);
    }
  }
  size_t r = row0 + row;
  #pragma unroll
  for (int i=0;i<4;i++){
    int d = q*4+i;
    g_h[r*DG+d]    = ha[i] + msgb[d];
    g_gate[r*DG+d] = 1.f/(1.f+expf(-(ga[i]+gateb[d])));
  }
}

// ---------------- gated aggregation ----
__global__ void k_agg(){
  int b = blockIdx.y;
  int n = blockIdx.x*16 + (threadIdx.x>>4);
  int d = threadIdx.x & 15;
  const float* hb = g_h + (size_t)b*NNODE*DG;
  float acc = 0.f;
  int base = n*KE;
  #pragma unroll
  for (int k=0;k<KE;k++){
    if (g_maskv[base+k] > 0.f) acc += hb[(size_t)g_cols[base+k]*DG + d];
  }
  int e0 = g_ptr[n], e1 = g_ptr[n+1];
  for (int e=e0; e<e1; e++) acc += hb[(size_t)g_rsrc[e]*DG + d];
  size_t idx = ((size_t)b*NNODE + n)*DG + d;
  g_xgg[idx] = g_gate[idx]*acc;
}

// ---------------- xx2 = xgg@lin2^T+b+residual; partial stats ----
__global__ void __launch_bounds__(256) k_gemm_lin2(
    const float* __restrict__ l2w, const float* __restrict__ l2b,
    const float* __restrict__ xin){
  __shared__ float sA[64*17];
  __shared__ float sW[96*17];
  __shared__ float rb[16];
  const int tid = threadIdx.x;
  const size_t row0 = (size_t)blockIdx.x*64;
  for (int i=tid;i<64*16;i+=256)
    sA[(i>>4)*17 + (i&15)] = g_xgg[row0*DG + i];
  for (int i=tid;i<96*16;i+=256)
    sW[(i>>4)*17 + (i&15)] = l2w[i];
  __syncthreads();
  const int cx = tid & 15, ry = tid >> 4;
  float acc[24];
  #pragma unroll
  for (int i=0;i<24;i++) acc[i]=0.f;
  #pragma unroll
  for (int k=0;k<16;k++){
    float a[4];
    #pragma unroll
    for (int j=0;j<4;j++) a[j]=sA[(ry*4+j)*17+k];
    #pragma unroll
    for (int i=0;i<6;i++){
      float w = sW[(cx*6+i)*17+k];
      #pragma unroll
      for (int j=0;j<4;j++) acc[j*6+i] = fmaf(a[j], w, acc[j*6+i]);
    }
  }
  float ls=0.f, ls2=0.f;
  #pragma unroll
  for (int j=0;j<4;j++){
    size_t row = row0 + ry*4 + j;
    #pragma unroll
    for (int i=0;i<6;i++){
      int c = cx*6 + i;
      size_t g = row*96 + c;
      float v = acc[j*6+i] + l2b[c] + xin[g];
      g_xx2[g] = v;
      ls += v; ls2 = fmaf(v, v, ls2);
    }
  }
  #pragma unroll
  for (int o=16;o;o>>=1){
    ls  += __shfl_xor_sync(0xffffffffu, ls,  o);
    ls2 += __shfl_xor_sync(0xffffffffu, ls2, o);
  }
  int warp = tid>>5, lane = tid&31;
  if (lane==0){ rb[warp]=ls; rb[8+warp]=ls2; }
  __syncthreads();
  if (tid==0){
    float s=0.f, s2=0.f;
    #pragma unroll
    for (int i=0;i<8;i++){ s+=rb[i]; s2+=rb[8+i]; }
    g_part[blockIdx.x*2]   = s;
    g_part[blockIdx.x*2+1] = s2;
  }
}

__global__ void k_stats(){
  int t = threadIdx.x;
  int b = t >> 5, j = t & 31;
  float s  = g_part[(b*32+j)*2];
  float s2 = g_part[(b*32+j)*2+1];
  #pragma unroll
  for (int o=16;o;o>>=1){
    s  += __shfl_xor_sync(0xffffffffu, s,  o);
    s2 += __shfl_xor_sync(0xffffffffu, s2, o);
  }
  if (j==0){
    const float inv = 1.f/(float)((size_t)NNODE*TT);
    float mu = s*inv;
    float var = s2*inv - mu*mu;
    g_mu[b] = mu;
    g_rstd[b] = rsqrtf(var + 1e-5f);
  }
}

// ---------------- k_tail: LN -> e1 GEMM + skip + relu (smem) -> l3/l4 head -> out ----
__global__ void __launch_bounds__(256) k_tail(
    const float* __restrict__ e1w, const float* __restrict__ e1b,
    const float* __restrict__ lnw, const float* __restrict__ lnb,
    const float* __restrict__ l3w, const float* __restrict__ l3b,
    const float* __restrict__ l4w, const float* __restrict__ l4b,
    float* __restrict__ out){
  extern __shared__ float sm[];
  float* sA = sm;            // 64*97
  float* sW = sA + 64*97;    // 96*97
  const int tid = threadIdx.x;
  const size_t row0 = (size_t)blockIdx.x*64;
  const int b = (int)(row0 >> 11);
  const float mu = g_mu[b], rstd = g_rstd[b];
  for (int i=tid;i<64*96;i+=256){
    int r=i/96, c=i-r*96;
    size_t row = row0+r; int n = (int)(row & (NNODE-1));
    float v = g_xx2[row*96+c];
    sA[r*97+c] = fmaf((v-mu)*rstd, lnw[n*96+c], lnb[n*96+c]);
  }
  for (int i=tid;i<96*96;i+=256){
    int r=i/96, c=i-r*96;
    sW[r*97+c] = e1w[i];
  }
  __syncthreads();
  const int cx = tid & 15, ry = tid >> 4;
  float acc[24];
  {
    const float* A = sA + ry*4*97;
    const float* W = sW + cx*6*97;
    #pragma unroll
    for (int i=0;i<24;i++) acc[i]=0.f;
    #pragma unroll 2
    for (int k=0;k<96;k++){
      float a[4];
      #pragma unroll
      for (int j=0;j<4;j++) a[j]=A[j*97+k];
      #pragma unroll
      for (int i=0;i<6;i++){
        float w = W[i*97+k];
        #pragma unroll
        for (int j=0;j<4;j++) acc[j*6+i] = fmaf(a[j], w, acc[j*6+i]);
      }
    }
  }
  __syncthreads();
  #pragma unroll
  for (int j=0;j<4;j++){
    size_t row = row0 + ry*4 + j;
    float s1v = g_s1[row];
    #pragma unroll
    for (int i=0;i<6;i++){
      int c = cx*6 + i;
      float v = acc[j*6+i] + e1b[c] + g_skipA[row*96+c] + s1v;
      sA[(ry*4+j)*97 + c] = fmaxf(v, 0.f);
    }
  }
  for (int i=tid;i<64*96;i+=256){
    int r=i/96, c=i-r*96;
    sW[r*97+c] = l3w[i];
  }
  __syncthreads();
  float acc2[16];
  {
    const float* A = sA + ry*4*97;
    const float* W = sW + cx*4*97;
    #pragma unroll
    for (int i=0;i<16;i++) acc2[i]=0.f;
    #pragma unroll 2
    for (int k=0;k<96;k++){
      float a[4];
      #pragma unroll
      for (int j=0;j<4;j++) a[j]=A[j*97+k];
      #pragma unroll
      for (int i=0;i<4;i++){
        float w = W[i*97+k];
        #pragma unroll
        for (int j=0;j<4;j++) acc2[j*4+i] = fmaf(a[j], w, acc2[j*4+i]);
      }
    }
  }
  float part[4];
  #pragma unroll
  for (int j=0;j<4;j++){
    float s = 0.f;
    #pragma unroll
    for (int i=0;i<4;i++){
      int c = cx*4 + i;
      float y = fmaxf(acc2[j*4+i] + l3b[c], 0.f);
      s = fmaf(y, l4w[c], s);
    }
    part[j] = s;
  }
  #pragma unroll
  for (int j=0;j<4;j++){
    #pragma unroll
    for (int o=8;o;o>>=1) part[j] += __shfl_xor_sync(0xffffffffu, part[j], o);
  }
  if (cx==0){
    #pragma unroll
    for (int j=0;j<4;j++)
      out[row0 + ry*4 + j] = part[j] + l4b[0];
  }
}

extern "C" void kernel_launch(void* const* d_in, const int* in_sizes, int n_in,
                              void* d_out, int out_size) {
  const float* x    = (const float*)d_in[0];
  const float* emb1 = (const float*)d_in[1];
  const float* emb2 = (const float*)d_in[2];
  const float* gc_w1= (const float*)d_in[3];
  const float* gc_b1= (const float*)d_in[4];
  const float* gc_w2= (const float*)d_in[5];
  const float* gc_b2= (const float*)d_in[6];
  const float* sk0w = (const float*)d_in[7];
  const float* sk0b = (const float*)d_in[8];
  const float* sk1w = (const float*)d_in[9];
  const float* sk1b = (const float*)d_in[10];
  const float* e1w  = (const float*)d_in[11];
  const float* e1b  = (const float*)d_in[12];
  const float* lsw  = (const float*)d_in[13];
  const float* lsb  = (const float*)d_in[14];
  const float* ltw  = (const float*)d_in[15];
  const float* ltb  = (const float*)d_in[16];
  const float* l1w  = (const float*)d_in[17];
  const float* l1b  = (const float*)d_in[18];
  const float* l2w  = (const float*)d_in[19];
  const float* l2b  = (const float*)d_in[20];
  const float* l3w  = (const float*)d_in[21];
  const float* l3b  = (const float*)d_in[22];
  const float* l4w  = (const float*)d_in[23];
  const float* l4b  = (const float*)d_in[24];
  const float* msgw = (const float*)d_in[25];
  const float* msgb = (const float*)d_in[26];
  const float* gatew= (const float*)d_in[27];
  const float* gateb= (const float*)d_in[28];
  const float* lnw  = (const float*)d_in[29];
  const float* lnb  = (const float*)d_in[30];
  float* out = (float*)d_out;

  static cudaStream_t s2 = nullptr;
  static cudaEvent_t  e0 = nullptr, e1 = nullptr;
  if (!s2){
    cudaStreamCreateWithFlags(&s2, cudaStreamNonBlocking);
    cudaEventCreateWithFlags(&e0, cudaEventDisableTiming);
    cudaEventCreateWithFlags(&e1, cudaEventDisableTiming);
  }

  const int SM1  = (64*97*2 + 48*97*3)*4;  // k_gemm1: 105.5KB
  const int SMXG = (64*97*2)*4;            // k_xg:    49.7KB
  const int SMT  = (64*97 + 96*97)*4;      // k_tail:  62.1KB
  cudaFuncSetAttribute(k_gemm1, cudaFuncAttributeMaxDynamicSharedMemorySize, SM1);
  cudaFuncSetAttribute(k_xg,    cudaFuncAttributeMaxDynamicSharedMemorySize, SMXG);
  cudaFuncSetAttribute(k_tail,  cudaFuncAttributeMaxDynamicSharedMemorySize, SMT);

  // fork: graph chain on s2, dense chain on legacy stream
  cudaEventRecord(e0, 0);
  cudaStreamWaitEvent(s2, e0, 0);
  k_graphpre<<<684, 256, 0, s2>>>(emb1, emb2, gc_w1, gc_b1, gc_w2, gc_b2, ltw, lsw);
  k_adj<<<dim3(NNODE/64, NNODE/64), 256, 0, s2>>>();
  k_topk<<<NNODE, 256, 0, s2>>>();
  k_scan<<<1, 1024, 0, s2>>>();
  k_fill<<<(NNODE*KE+255)/256, 256, 0, s2>>>();
  cudaEventRecord(e1, s2);

  k_decomp<<<NROWS/4, dim3(TT,4)>>>(x);
  k_gemm1<<<dim3(NROWS/64, 2), 256, SM1>>>(x, sk0w, sk0b, lsw, lsb, ltb);
  k_xg<<<NROWS/64, 256, SMXG>>>(l1w, l1b, sk1w, sk1b, msgw, msgb, gatew, gateb);

  // join: agg needs graph chain + h
  cudaStreamWaitEvent(0, e1, 0);
  k_agg<<<dim3(NNODE/16, NB), 256>>>();
  k_gemm_lin2<<<NROWS/64, 256>>>(l2w, l2b, x);
  k_stats<<<1, 1024>>>();
  k_tail<<<NROWS/64, 256, SMT>>>(e1w, e1b, lnw, lnb, l3w, l3b, l4w, l4b, out);
}

// round 16
// speedup vs baseline: 1.5606x; 1.5606x over previous
#include <cuda_runtime.h>
#include <math.h>

#define NB 32
#define NNODE 2048
#define TT 96
#define KE 20
#define DNODE 40
#define DH 64
#define DG 16
#define NROWS (NB*NNODE)

// ---------------- scratch ----------
__device__ float g_nv1[NNODE*DNODE];
__device__ float g_nv2[NNODE*DNODE];
__device__ float g_Wd[TT*TT];
__device__ float g_adj[(size_t)NNODE*NNODE];
__device__ int   g_cols[NNODE*KE];
__device__ float g_maskv[NNODE*KE];
__device__ int   g_cnt[NNODE];
__device__ int   g_cnt2[NNODE];
__device__ int   g_ptr[NNODE+1];
__device__ int   g_rsrc[NNODE*KE];
__device__ float g_xx[(size_t)NROWS*TT];
__device__ float g_skipA[(size_t)NROWS*TT];
__device__ float g_s1[NROWS];
__device__ float g_h[(size_t)NROWS*DG];
__device__ float g_gate[(size_t)NROWS*DG];
__device__ float g_xgg[(size_t)NROWS*DG];
__device__ float g_xx2[(size_t)NROWS*TT];
__device__ float g_part[2048];
__device__ float g_mu[NB];
__device__ float g_rstd[NB];

// ---------------- XLA EmitTanh f32: rational, clamp +-7.99881172180175781 ----
__device__ __forceinline__ float xtanh(float x){
  const float kClamp = 7.99881172180175781f;
  float xc = fminf(fmaxf(x, -kClamp), kClamp);
  float x2 = xc*xc;
  float p = fmaf(x2, -2.76076847742355e-16f, 2.00018790482477e-13f);
  p = fmaf(x2, p, -8.60467152213735e-11f);
  p = fmaf(x2, p,  5.12229709037114e-08f);
  p = fmaf(x2, p,  1.48572235717979e-05f);
  p = fmaf(x2, p,  6.37261928875436e-04f);
  p = fmaf(x2, p,  4.89352455891786e-03f);
  p = xc * p;
  float q = fmaf(x2, 1.19825839466702e-06f, 1.18534705686654e-04f);
  q = fmaf(x2, q, 2.26843463243900e-03f);
  q = fmaf(x2, q, 4.89352518554385e-03f);
  return (fabsf(x) < 0.0004f) ? x : (p/q);
}

// ---------------- graph pre: nv1 | nv2 | Wd | zero-cnt in one launch ----
__global__ void k_graphpre(const float* __restrict__ emb1, const float* __restrict__ emb2,
                           const float* __restrict__ w1, const float* __restrict__ b1,
                           const float* __restrict__ w2, const float* __restrict__ b2,
                           const float* __restrict__ wt, const float* __restrict__ wsm){
  int bx = blockIdx.x;
  if (bx < 640){
    int which = bx >= 320;
    int idx = (which ? bx-320 : bx)*256 + threadIdx.x;
    int i = idx / DNODE, j = idx - i*DNODE;
    const float* e  = (which ? emb2 : emb1) + i*DNODE;
    const float* wr = (which ? w2 : w1) + j*DNODE;
    const float* bb = which ? b2 : b1;
    float s = 0.f;
    #pragma unroll
    for (int k=0;k<DNODE;k++) s = fmaf(e[k], wr[k], s);
    float v = xtanh(3.0f*(s + bb[j]));
    if (which) g_nv2[idx] = v; else g_nv1[idx] = v;
  } else if (bx < 676){
    int i = (bx-640)*256 + threadIdx.x;
    if (i < TT*TT) g_Wd[i] = wt[i] - wsm[i];
  } else {
    int i = (bx-676)*256 + threadIdx.x;
    if (i < NNODE){ g_cnt[i]=0; g_cnt2[i]=0; }
  }
}

// 64x64 tile, 4x4 micro-tile per thread, transposed smem [k][row] pad-65.
__global__ void __launch_bounds__(256) k_adj(){
  __shared__ float sA1[DNODE*65], sA2[DNODE*65], sB1[DNODE*65], sB2[DNODE*65];
  const int tid = threadIdx.x;
  const int i0 = blockIdx.y*64, j0 = blockIdx.x*64;
  for (int idx=tid; idx<64*DNODE; idx+=256){
    int r = idx/DNODE, k = idx - r*DNODE;
    sA1[k*65+r] = g_nv1[(i0+r)*DNODE+k];
    sA2[k*65+r] = g_nv2[(i0+r)*DNODE+k];
    sB1[k*65+r] = g_nv1[(j0+r)*DNODE+k];
    sB2[k*65+r] = g_nv2[(j0+r)*DNODE+k];
  }
  __syncthreads();
  const int tx = tid & 15, ty = tid >> 4;
  float p[16], q[16];
  #pragma unroll
  for (int i=0;i<16;i++){ p[i]=0.f; q[i]=0.f; }
  #pragma unroll 4
  for (int k=0;k<DNODE;k++){
    float a1[4], a2[4], b1[4], b2[4];
    #pragma unroll
    for (int i=0;i<4;i++){
      a1[i] = sA1[k*65 + ty*4+i];
      a2[i] = sA2[k*65 + ty*4+i];
      b1[i] = sB1[k*65 + tx*4+i];
      b2[i] = sB2[k*65 + tx*4+i];
    }
    #pragma unroll
    for (int i=0;i<4;i++)
      #pragma unroll
      for (int j=0;j<4;j++){
        p[i*4+j] = fmaf(a1[i], b2[j], p[i*4+j]);
        q[i*4+j] = fmaf(a2[i], b1[j], q[i*4+j]);
      }
  }
  #pragma unroll
  for (int i=0;i<4;i++){
    size_t rowo = (size_t)(i0 + ty*4 + i)*NNODE + j0 + tx*4;
    #pragma unroll
    for (int j=0;j<4;j++){
      float t = xtanh(3.0f*(p[i*4+j]-q[i*4+j]));
      g_adj[rowo + j] = fmaxf(t, 0.f);
    }
  }
}

// ---------------- top-k + fused degree count (ties -> lowest index) ----
__global__ void k_topk(){
  __shared__ unsigned long long red[8];
  __shared__ unsigned long long s_win;
  const int row = blockIdx.x, tid = threadIdx.x;
  const float* ar = g_adj + (size_t)row*NNODE;
  unsigned long long key[8];
  #pragma unroll
  for (int j=0;j<8;j++){
    int i = j*256 + tid;
    unsigned int b = __float_as_uint(ar[i]);
    b = (b & 0x80000000u) ? ~b : (b | 0x80000000u);
    key[j] = ((unsigned long long)b<<32) | (unsigned int)(NNODE-1-i);
  }
  for (int k=0;k<KE;k++){
    unsigned long long best = key[0];
    #pragma unroll
    for (int j=1;j<8;j++) best = best > key[j] ? best : key[j];
    #pragma unroll
    for (int o=16;o;o>>=1){
      unsigned long long other = __shfl_xor_sync(0xffffffffu, best, o);
      if (other > best) best = other;
    }
    if ((tid&31)==0) red[tid>>5] = best;
    __syncthreads();
    if (tid==0){
      unsigned long long bb = red[0];
      #pragma unroll
      for (int i=1;i<8;i++) if (red[i] > bb) bb = red[i];
      s_win = bb;
      int idx = NNODE-1-(int)(bb & 0xffffffffull);
      bool pos = ((unsigned int)(bb>>32) > 0x80000000u);
      g_cols[row*KE+k]  = idx;
      g_maskv[row*KE+k] = pos ? 1.f : 0.f;
      if (pos) atomicAdd(&g_cnt[idx], 1);
    }
    __syncthreads();
    int idx = NNODE-1-(int)(s_win & 0xffffffffull);
    if ((idx & 255) == tid) key[idx>>8] = 0ull;
  }
}

// ---------------- scan: 1 block over 2048 counts ----
__global__ void k_scan(){
  __shared__ int sa[NNODE], sb[NNODE];
  const int t = threadIdx.x;    // 1024
  sa[t] = g_cnt[t]; sa[t+1024] = g_cnt[t+1024];
  __syncthreads();
  int *src=sa, *dst=sb;
  for (int off=1; off<NNODE; off<<=1){
    for (int i=t;i<NNODE;i+=1024){
      int v = src[i];
      if (i >= off) v += src[i-off];
      dst[i] = v;
    }
    __syncthreads();
    int* tmp=src; src=dst; dst=tmp;
  }
  if (t==0) g_ptr[0]=0;
  g_ptr[t+1] = src[t];
  g_ptr[t+1024+1] = src[t+1024];
}

// ---------------- fill: parallel ----
__global__ void k_fill(){
  int idx = blockIdx.x*256+threadIdx.x;
  if (idx >= NNODE*KE) return;
  if (g_maskv[idx] > 0.f){
    int n = idx/KE;
    int c = g_cols[idx];
    int s = atomicAdd(&g_cnt2[c], 1);
    g_rsrc[g_ptr[c]+s] = n;
  }
}

// ---------------- fused decomp + GEMM1 (N-split x2) ----
// m computed in-smem from x tile; xx = x@Ws^T + m@Wd^T + b; skipA = x@W0^T + b0
__global__ void __launch_bounds__(256) k_gemm1(
    const float* __restrict__ x,  const float* __restrict__ w0, const float* __restrict__ b0,
    const float* __restrict__ ws, const float* __restrict__ bs, const float* __restrict__ bt){
  extern __shared__ float sm[];
  float* sX  = sm;
  float* sM  = sX  + 64*97;
  float* sWs = sM  + 64*97;
  float* sWd = sWs + 48*97;
  float* sW0 = sWd + 48*97;
  const int tid = threadIdx.x;
  const size_t row0 = (size_t)blockIdx.x*64;
  const int c0 = blockIdx.y*48;
  for (int i=tid;i<64*96;i+=256){
    int r=i/96, c=i-r*96;
    sX[r*97+c] = x[(row0+r)*96 + c];
  }
  for (int i=tid;i<48*96;i+=256){
    int r=i/96, c=i-r*96;
    int gi = (c0+r)*96 + c;
    sWs[r*97+c] = ws[gi];
    sWd[r*97+c] = g_Wd[gi];
    sW0[r*97+c] = w0[gi];
  }
  __syncthreads();
  // ---- in-smem decomposition: 4 threads per row, 24 positions each ----
  const int dr = tid >> 2, dq = tid & 3;       // row 0..63, quarter 0..3
  const float* xr = sX + dr*97;
  float ma1[24];
  {
    float* st = sM + dr*97;
    #pragma unroll
    for (int u=0;u<24;u++){
      int t = dq*24 + u;
      float s = 0.f;
      #pragma unroll
      for (int d=-12; d<=12; d++){
        int j = t+d; j = max(0, min(TT-1, j));
        s += xr[j];
      }
      ma1[u] = s / 25.0f;
      st[t] = xr[t] - ma1[u];
    }
  }
  __syncthreads();
  {
    const float* st = sM + dr*97;
    float mloc[24];
    #pragma unroll
    for (int u=0;u<24;u++){
      int t = dq*24 + u;
      float s = 0.f;
      #pragma unroll
      for (int d=-12; d<=12; d++){
        int j = t+d; j = max(0, min(TT-1, j));
        s += st[j];
      }
      mloc[u] = ma1[u] + s / 25.0f;
    }
    __syncthreads();   // all st reads done before overwrite
    float* mrow = sM + dr*97;
    #pragma unroll
    for (int u=0;u<24;u++) mrow[dq*24+u] = mloc[u];
  }
  __syncthreads();
  // ---- GEMM ----
  const int cx = tid & 15, ry = tid >> 4;
  const float* A   = sX  + ry*4*97;
  const float* M   = sM  + ry*4*97;
  const float* Wsp = sWs + cx*3*97;
  const float* Wdp = sWd + cx*3*97;
  const float* W0p = sW0 + cx*3*97;
  float aX[12], aS[12];
  #pragma unroll
  for (int i=0;i<12;i++){ aX[i]=0.f; aS[i]=0.f; }
  #pragma unroll 2
  for (int k=0;k<96;k++){
    float xv[4], mv[4];
    #pragma unroll
    for (int j=0;j<4;j++){ xv[j]=A[j*97+k]; mv[j]=M[j*97+k]; }
    #pragma unroll
    for (int i=0;i<3;i++){
      float fws=Wsp[i*97+k], fwd=Wdp[i*97+k], fw0=W0p[i*97+k];
      #pragma unroll
      for (int j=0;j<4;j++){
        aX[j*3+i] = fmaf(xv[j], fws, fmaf(mv[j], fwd, aX[j*3+i]));
        aS[j*3+i] = fmaf(xv[j], fw0, aS[j*3+i]);
      }
    }
  }
  #pragma unroll
  for (int j=0;j<4;j++){
    size_t row = row0 + ry*4 + j;
    #pragma unroll
    for (int i=0;i<3;i++){
      int c = c0 + cx*3 + i;
      size_t g = row*96 + c;
      g_xx[g]    = aX[j*3+i] + bs[c] + bt[c];
      g_skipA[g] = aS[j*3+i] + b0[c];
    }
  }
}

// ---------------- k_xg: xg = xx@lin1^T+b (smem) ; s1 ; h,gate from smem xg ----
__global__ void __launch_bounds__(256) k_xg(
    const float* __restrict__ l1w, const float* __restrict__ l1b,
    const float* __restrict__ s1w, const float* __restrict__ s1b,
    const float* __restrict__ msgw, const float* __restrict__ msgb,
    const float* __restrict__ gatew, const float* __restrict__ gateb){
  extern __shared__ float sm[];
  float* sA = sm;            // 64*97 xx
  float* sW = sA + 64*97;    // 64*97 l1w; later reused as xg tile [64][65]
  __shared__ float sMW[2*DG*DH];
  const int tid = threadIdx.x;
  const size_t row0 = (size_t)blockIdx.x*64;
  for (int i=tid;i<64*96;i+=256){
    int r=i/96, c=i-r*96;
    sA[r*97+c] = g_xx[(row0+r)*96 + c];
    sW[r*97+c] = l1w[i];
  }
  for (int i=tid;i<DG*DH;i+=256){
    sMW[i] = msgw[i];
    sMW[DG*DH + i] = gatew[i];
  }
  __syncthreads();
  const int cx = tid & 15, ry = tid >> 4;
  {
    const float* A = sA + ry*4*97;
    const float* W = sW + cx*4*97;
    float acc[16];
    #pragma unroll
    for (int i=0;i<16;i++) acc[i]=0.f;
    #pragma unroll 2
    for (int k=0;k<96;k++){
      float a[4];
      #pragma unroll
      for (int j=0;j<4;j++) a[j]=A[j*97+k];
      #pragma unroll
      for (int i=0;i<4;i++){
        float w = W[i*97+k];
        #pragma unroll
        for (int j=0;j<4;j++) acc[j*4+i] = fmaf(a[j], w, acc[j*4+i]);
      }
    }
    if (tid < 64){
      float s = 0.f;
      #pragma unroll 4
      for (int k=0;k<96;k++) s = fmaf(sA[tid*97+k], s1w[k], s);
      g_s1[row0+tid] = s + s1b[0];
    }
    __syncthreads();
    #pragma unroll
    for (int j=0;j<4;j++)
      #pragma unroll
      for (int i=0;i<4;i++)
        sW[(ry*4+j)*65 + cx*4+i] = acc[j*4+i] + l1b[cx*4+i];
  }
  __syncthreads();
  const int row = tid >> 2, q = tid & 3;
  float ha[4] = {0,0,0,0}, ga[4] = {0,0,0,0};
  #pragma unroll 4
  for (int k=0;k<DH;k++){
    float xv = sW[row*65+k];
    #pragma unroll
    for (int i=0;i<4;i++){
      ha[i] = fmaf(xv, sMW[(q*4+i)*DH+k], ha[i]);
      ga[i] = fmaf(xv, sMW[DG*DH + (q*4+i)*DH+k], ga[i]);
    }
  }
  size_t r = row0 + row;
  #pragma unroll
  for (int i=0;i<4;i++){
    int d = q*4+i;
    g_h[r*DG+d]    = ha[i] + msgb[d];
    g_gate[r*DG+d] = 1.f/(1.f+expf(-(ga[i]+gateb[d])));
  }
}

// ---------------- gated aggregation ----
__global__ void k_agg(){
  int b = blockIdx.y;
  int n = blockIdx.x*16 + (threadIdx.x>>4);
  int d = threadIdx.x & 15;
  const float* hb = g_h + (size_t)b*NNODE*DG;
  float acc = 0.f;
  int base = n*KE;
  #pragma unroll
  for (int k=0;k<KE;k++){
    if (g_maskv[base+k] > 0.f) acc += hb[(size_t)g_cols[base+k]*DG + d];
  }
  int e0 = g_ptr[n], e1 = g_ptr[n+1];
  for (int e=e0; e<e1; e++) acc += hb[(size_t)g_rsrc[e]*DG + d];
  size_t idx = ((size_t)b*NNODE + n)*DG + d;
  g_xgg[idx] = g_gate[idx]*acc;
}

// ---------------- xx2 = xgg@lin2^T+b+residual; partial stats ----
__global__ void __launch_bounds__(256) k_gemm_lin2(
    const float* __restrict__ l2w, const float* __restrict__ l2b,
    const float* __restrict__ xin){
  __shared__ float sA[64*17];
  __shared__ float sW[96*17];
  __shared__ float rb[16];
  const int tid = threadIdx.x;
  const size_t row0 = (size_t)blockIdx.x*64;
  for (int i=tid;i<64*16;i+=256)
    sA[(i>>4)*17 + (i&15)] = g_xgg[row0*DG + i];
  for (int i=tid;i<96*16;i+=256)
    sW[(i>>4)*17 + (i&15)] = l2w[i];
  __syncthreads();
  const int cx = tid & 15, ry = tid >> 4;
  float acc[24];
  #pragma unroll
  for (int i=0;i<24;i++) acc[i]=0.f;
  #pragma unroll
  for (int k=0;k<16;k++){
    float a[4];
    #pragma unroll
    for (int j=0;j<4;j++) a[j]=sA[(ry*4+j)*17+k];
    #pragma unroll
    for (int i=0;i<6;i++){
      float w = sW[(cx*6+i)*17+k];
      #pragma unroll
      for (int j=0;j<4;j++) acc[j*6+i] = fmaf(a[j], w, acc[j*6+i]);
    }
  }
  float ls=0.f, ls2=0.f;
  #pragma unroll
  for (int j=0;j<4;j++){
    size_t row = row0 + ry*4 + j;
    #pragma unroll
    for (int i=0;i<6;i++){
      int c = cx*6 + i;
      size_t g = row*96 + c;
      float v = acc[j*6+i] + l2b[c] + xin[g];
      g_xx2[g] = v;
      ls += v; ls2 = fmaf(v, v, ls2);
    }
  }
  #pragma unroll
  for (int o=16;o;o>>=1){
    ls  += __shfl_xor_sync(0xffffffffu, ls,  o);
    ls2 += __shfl_xor_sync(0xffffffffu, ls2, o);
  }
  int warp = tid>>5, lane = tid&31;
  if (lane==0){ rb[warp]=ls; rb[8+warp]=ls2; }
  __syncthreads();
  if (tid==0){
    float s=0.f, s2=0.f;
    #pragma unroll
    for (int i=0;i<8;i++){ s+=rb[i]; s2+=rb[8+i]; }
    g_part[blockIdx.x*2]   = s;
    g_part[blockIdx.x*2+1] = s2;
  }
}

__global__ void k_stats(){
  int t = threadIdx.x;
  int b = t >> 5, j = t & 31;
  float s  = g_part[(b*32+j)*2];
  float s2 = g_part[(b*32+j)*2+1];
  #pragma unroll
  for (int o=16;o;o>>=1){
    s  += __shfl_xor_sync(0xffffffffu, s,  o);
    s2 += __shfl_xor_sync(0xffffffffu, s2, o);
  }
  if (j==0){
    const float inv = 1.f/(float)((size_t)NNODE*TT);
    float mu = s*inv;
    float var = s2*inv - mu*mu;
    g_mu[b] = mu;
    g_rstd[b] = rsqrtf(var + 1e-5f);
  }
}

// ---------------- k_tail: LN -> e1 GEMM + skip + relu (smem) -> l3/l4 head -> out ----
__global__ void __launch_bounds__(256) k_tail(
    const float* __restrict__ e1w, const float* __restrict__ e1b,
    const float* __restrict__ lnw, const float* __restrict__ lnb,
    const float* __restrict__ l3w, const float* __restrict__ l3b,
    const float* __restrict__ l4w, const float* __restrict__ l4b,
    float* __restrict__ out){
  extern __shared__ float sm[];
  float* sA = sm;            // 64*97
  float* sW = sA + 64*97;    // 96*97
  const int tid = threadIdx.x;
  const size_t row0 = (size_t)blockIdx.x*64;
  const int b = (int)(row0 >> 11);
  const float mu = g_mu[b], rstd = g_rstd[b];
  for (int i=tid;i<64*96;i+=256){
    int r=i/96, c=i-r*96;
    size_t row = row0+r; int n = (int)(row & (NNODE-1));
    float v = g_xx2[row*96+c];
    sA[r*97+c] = fmaf((v-mu)*rstd, lnw[n*96+c], lnb[n*96+c]);
  }
  for (int i=tid;i<96*96;i+=256){
    int r=i/96, c=i-r*96;
    sW[r*97+c] = e1w[i];
  }
  __syncthreads();
  const int cx = tid & 15, ry = tid >> 4;
  float acc[24];
  {
    const float* A = sA + ry*4*97;
    const float* W = sW + cx*6*97;
    #pragma unroll
    for (int i=0;i<24;i++) acc[i]=0.f;
    #pragma unroll 2
    for (int k=0;k<96;k++){
      float a[4];
      #pragma unroll
      for (int j=0;j<4;j++) a[j]=A[j*97+k];
      #pragma unroll
      for (int i=0;i<6;i++){
        float w = W[i*97+k];
        #pragma unroll
        for (int j=0;j<4;j++) acc[j*6+i] = fmaf(a[j], w, acc[j*6+i]);
      }
    }
  }
  __syncthreads();
  #pragma unroll
  for (int j=0;j<4;j++){
    size_t row = row0 + ry*4 + j;
    float s1v = g_s1[row];
    #pragma unroll
    for (int i=0;i<6;i++){
      int c = cx*6 + i;
      float v = acc[j*6+i] + e1b[c] + g_skipA[row*96+c] + s1v;
      sA[(ry*4+j)*97 + c] = fmaxf(v, 0.f);
    }
  }
  for (int i=tid;i<64*96;i+=256){
    int r=i/96, c=i-r*96;
    sW[r*97+c] = l3w[i];
  }
  __syncthreads();
  float acc2[16];
  {
    const float* A = sA + ry*4*97;
    const float* W = sW + cx*4*97;
    #pragma unroll
    for (int i=0;i<16;i++) acc2[i]=0.f;
    #pragma unroll 2
    for (int k=0;k<96;k++){
      float a[4];
      #pragma unroll
      for (int j=0;j<4;j++) a[j]=A[j*97+k];
      #pragma unroll
      for (int i=0;i<4;i++){
        float w = W[i*97+k];
        #pragma unroll
        for (int j=0;j<4;j++) acc2[j*4+i] = fmaf(a[j], w, acc2[j*4+i]);
      }
    }
  }
  float part[4];
  #pragma unroll
  for (int j=0;j<4;j++){
    float s = 0.f;
    #pragma unroll
    for (int i=0;i<4;i++){
      int c = cx*4 + i;
      float y = fmaxf(acc2[j*4+i] + l3b[c], 0.f);
      s = fmaf(y, l4w[c], s);
    }
    part[j] = s;
  }
  #pragma unroll
  for (int j=0;j<4;j++){
    #pragma unroll
    for (int o=8;o;o>>=1) part[j] += __shfl_xor_sync(0xffffffffu, part[j], o);
  }
  if (cx==0){
    #pragma unroll
    for (int j=0;j<4;j++)
      out[row0 + ry*4 + j] = part[j] + l4b[0];
  }
}

extern "C" void kernel_launch(void* const* d_in, const int* in_sizes, int n_in,
                              void* d_out, int out_size) {
  const float* x    = (const float*)d_in[0];
  const float* emb1 = (const float*)d_in[1];
  const float* emb2 = (const float*)d_in[2];
  const float* gc_w1= (const float*)d_in[3];
  const float* gc_b1= (const float*)d_in[4];
  const float* gc_w2= (const float*)d_in[5];
  const float* gc_b2= (const float*)d_in[6];
  const float* sk0w = (const float*)d_in[7];
  const float* sk0b = (const float*)d_in[8];
  const float* sk1w = (const float*)d_in[9];
  const float* sk1b = (const float*)d_in[10];
  const float* e1w  = (const float*)d_in[11];
  const float* e1b  = (const float*)d_in[12];
  const float* lsw  = (const float*)d_in[13];
  const float* lsb  = (const float*)d_in[14];
  const float* ltw  = (const float*)d_in[15];
  const float* ltb  = (const float*)d_in[16];
  const float* l1w  = (const float*)d_in[17];
  const float* l1b  = (const float*)d_in[18];
  const float* l2w  = (const float*)d_in[19];
  const float* l2b  = (const float*)d_in[20];
  const float* l3w  = (const float*)d_in[21];
  const float* l3b  = (const float*)d_in[22];
  const float* l4w  = (const float*)d_in[23];
  const float* l4b  = (const float*)d_in[24];
  const float* msgw = (const float*)d_in[25];
  const float* msgb = (const float*)d_in[26];
  const float* gatew= (const float*)d_in[27];
  const float* gateb= (const float*)d_in[28];
  const float* lnw  = (const float*)d_in[29];
  const float* lnb  = (const float*)d_in[30];
  float* out = (float*)d_out;

  const int SM1  = (64*97*2 + 48*97*3)*4;  // k_gemm1: 105.5KB
  const int SMXG = (64*97*2)*4;            // k_xg:    49.7KB
  const int SMT  = (64*97 + 96*97)*4;      // k_tail:  62.1KB
  cudaFuncSetAttribute(k_gemm1, cudaFuncAttributeMaxDynamicSharedMemorySize, SM1);
  cudaFuncSetAttribute(k_xg,    cudaFuncAttributeMaxDynamicSharedMemorySize, SMXG);
  cudaFuncSetAttribute(k_tail,  cudaFuncAttributeMaxDynamicSharedMemorySize, SMT);

  // graph construction (bit-exact path)
  k_graphpre<<<684, 256>>>(emb1, emb2, gc_w1, gc_b1, gc_w2, gc_b2, ltw, lsw);
  k_adj<<<dim3(NNODE/64, NNODE/64), 256>>>();
  k_topk<<<NNODE, 256>>>();
  k_scan<<<1, 1024>>>();
  k_fill<<<(NNODE*KE+255)/256, 256>>>();
  // dense chain (decomp fused into gemm1)
  k_gemm1<<<dim3(NROWS/64, 2), 256, SM1>>>(x, sk0w, sk0b, lsw, lsb, ltb);
  k_xg<<<NROWS/64, 256, SMXG>>>(l1w, l1b, sk1w, sk1b, msgw, msgb, gatew, gateb);
  k_agg<<<dim3(NNODE/16, NB), 256>>>();
  k_gemm_lin2<<<NROWS/64, 256>>>(l2w, l2b, x);
  k_stats<<<1, 1024>>>();
  k_tail<<<NROWS/64, 256, SMT>>>(e1w, e1b, lnw, lnb, l3w, l3b, l4w, l4b, out);
}

// round 17
// speedup vs baseline: 1.5722x; 1.0074x over previous
#include <cuda_runtime.h>
#include <math.h>

#define NB 32
#define NNODE 2048
#define TT 96
#define KE 20
#define DNODE 40
#define DH 64
#define DG 16
#define NROWS (NB*NNODE)

// ---------------- scratch ----------
__device__ float g_nv1[NNODE*DNODE];
__device__ float g_nv2[NNODE*DNODE];
__device__ float g_Wd[TT*TT];
__device__ float g_adj[(size_t)NNODE*NNODE];
__device__ int   g_cols[NNODE*KE];
__device__ float g_maskv[NNODE*KE];
__device__ int   g_cnt[NNODE];
__device__ int   g_cnt2[NNODE];
__device__ int   g_ptr[NNODE+1];
__device__ int   g_rsrc[NNODE*KE];
__device__ float g_xx[(size_t)NROWS*TT];
__device__ float g_skipA[(size_t)NROWS*TT];
__device__ float g_s1[NROWS];
__device__ float g_h[(size_t)NROWS*DG];
__device__ float g_gate[(size_t)NROWS*DG];
__device__ float g_xgg[(size_t)NROWS*DG];
__device__ float g_xx2[(size_t)NROWS*TT];
__device__ float g_part[2048];
__device__ float g_mu[NB];
__device__ float g_rstd[NB];

// ---------------- XLA EmitTanh f32: rational, clamp +-7.99881172180175781 ----
__device__ __forceinline__ float xtanh(float x){
  const float kClamp = 7.99881172180175781f;
  float xc = fminf(fmaxf(x, -kClamp), kClamp);
  float x2 = xc*xc;
  float p = fmaf(x2, -2.76076847742355e-16f, 2.00018790482477e-13f);
  p = fmaf(x2, p, -8.60467152213735e-11f);
  p = fmaf(x2, p,  5.12229709037114e-08f);
  p = fmaf(x2, p,  1.48572235717979e-05f);
  p = fmaf(x2, p,  6.37261928875436e-04f);
  p = fmaf(x2, p,  4.89352455891786e-03f);
  p = xc * p;
  float q = fmaf(x2, 1.19825839466702e-06f, 1.18534705686654e-04f);
  q = fmaf(x2, q, 2.26843463243900e-03f);
  q = fmaf(x2, q, 4.89352518554385e-03f);
  return (fabsf(x) < 0.0004f) ? x : (p/q);
}

// ---------------- graph pre: nv1 | nv2 | Wd | zero-cnt in one launch ----
__global__ void k_graphpre(const float* __restrict__ emb1, const float* __restrict__ emb2,
                           const float* __restrict__ w1, const float* __restrict__ b1,
                           const float* __restrict__ w2, const float* __restrict__ b2,
                           const float* __restrict__ wt, const float* __restrict__ wsm){
  int bx = blockIdx.x;
  if (bx < 640){
    int which = bx >= 320;
    int idx = (which ? bx-320 : bx)*256 + threadIdx.x;
    int i = idx / DNODE, j = idx - i*DNODE;
    const float* e  = (which ? emb2 : emb1) + i*DNODE;
    const float* wr = (which ? w2 : w1) + j*DNODE;
    const float* bb = which ? b2 : b1;
    float s = 0.f;
    #pragma unroll
    for (int k=0;k<DNODE;k++) s = fmaf(e[k], wr[k], s);
    float v = xtanh(3.0f*(s + bb[j]));
    if (which) g_nv2[idx] = v; else g_nv1[idx] = v;
  } else if (bx < 676){
    int i = (bx-640)*256 + threadIdx.x;
    if (i < TT*TT) g_Wd[i] = wt[i] - wsm[i];
  } else {
    int i = (bx-676)*256 + threadIdx.x;
    if (i < NNODE){ g_cnt[i]=0; g_cnt2[i]=0; }
  }
}

// ---------------- k_m1: adj (blocks 0..1023) | decomp+gemm1 (blocks 1024..3071) ----
__global__ void __launch_bounds__(256) k_m1(
    const float* __restrict__ x,  const float* __restrict__ w0, const float* __restrict__ b0,
    const float* __restrict__ ws, const float* __restrict__ bs, const float* __restrict__ bt){
  extern __shared__ float sm[];
  const int bx = blockIdx.x;
  const int tid = threadIdx.x;
  if (bx < 1024){
    // ---- adjacency 64x64 tile ----
    float* sA1 = sm;
    float* sA2 = sA1 + DNODE*65;
    float* sB1 = sA2 + DNODE*65;
    float* sB2 = sB1 + DNODE*65;
    const int i0 = (bx >> 5)*64, j0 = (bx & 31)*64;
    for (int idx=tid; idx<64*DNODE; idx+=256){
      int r = idx/DNODE, k = idx - r*DNODE;
      sA1[k*65+r] = g_nv1[(i0+r)*DNODE+k];
      sA2[k*65+r] = g_nv2[(i0+r)*DNODE+k];
      sB1[k*65+r] = g_nv1[(j0+r)*DNODE+k];
      sB2[k*65+r] = g_nv2[(j0+r)*DNODE+k];
    }
    __syncthreads();
    const int tx = tid & 15, ty = tid >> 4;
    float p[16], q[16];
    #pragma unroll
    for (int i=0;i<16;i++){ p[i]=0.f; q[i]=0.f; }
    #pragma unroll 4
    for (int k=0;k<DNODE;k++){
      float a1[4], a2[4], b1[4], b2[4];
      #pragma unroll
      for (int i=0;i<4;i++){
        a1[i] = sA1[k*65 + ty*4+i];
        a2[i] = sA2[k*65 + ty*4+i];
        b1[i] = sB1[k*65 + tx*4+i];
        b2[i] = sB2[k*65 + tx*4+i];
      }
      #pragma unroll
      for (int i=0;i<4;i++)
        #pragma unroll
        for (int j=0;j<4;j++){
          p[i*4+j] = fmaf(a1[i], b2[j], p[i*4+j]);
          q[i*4+j] = fmaf(a2[i], b1[j], q[i*4+j]);
        }
    }
    #pragma unroll
    for (int i=0;i<4;i++){
      size_t rowo = (size_t)(i0 + ty*4 + i)*NNODE + j0 + tx*4;
      #pragma unroll
      for (int j=0;j<4;j++){
        float t = xtanh(3.0f*(p[i*4+j]-q[i*4+j]));
        g_adj[rowo + j] = fmaxf(t, 0.f);
      }
    }
  } else {
    // ---- fused decomp + gemm1 ----
    float* sX  = sm;
    float* sM  = sX  + 64*97;
    float* sWs = sM  + 64*97;
    float* sWd = sWs + 48*97;
    float* sW0 = sWd + 48*97;
    const int gb = bx - 1024;
    const size_t row0 = (size_t)(gb & 1023)*64;
    const int c0 = (gb >> 10)*48;
    for (int i=tid;i<64*96;i+=256){
      int r=i/96, c=i-r*96;
      sX[r*97+c] = x[(row0+r)*96 + c];
    }
    for (int i=tid;i<48*96;i+=256){
      int r=i/96, c=i-r*96;
      int gi = (c0+r)*96 + c;
      sWs[r*97+c] = ws[gi];
      sWd[r*97+c] = g_Wd[gi];
      sW0[r*97+c] = w0[gi];
    }
    __syncthreads();
    const int dr = tid >> 2, dq = tid & 3;
    const float* xr = sX + dr*97;
    float ma1[24];
    {
      float* st = sM + dr*97;
      #pragma unroll
      for (int u=0;u<24;u++){
        int t = dq*24 + u;
        float s = 0.f;
        #pragma unroll
        for (int d=-12; d<=12; d++){
          int j = t+d; j = max(0, min(TT-1, j));
          s += xr[j];
        }
        ma1[u] = s / 25.0f;
        st[t] = xr[t] - ma1[u];
      }
    }
    __syncthreads();
    {
      const float* st = sM + dr*97;
      float mloc[24];
      #pragma unroll
      for (int u=0;u<24;u++){
        int t = dq*24 + u;
        float s = 0.f;
        #pragma unroll
        for (int d=-12; d<=12; d++){
          int j = t+d; j = max(0, min(TT-1, j));
          s += st[j];
        }
        mloc[u] = ma1[u] + s / 25.0f;
      }
      __syncthreads();
      float* mrow = sM + dr*97;
      #pragma unroll
      for (int u=0;u<24;u++) mrow[dq*24+u] = mloc[u];
    }
    __syncthreads();
    const int cx = tid & 15, ry = tid >> 4;
    const float* A   = sX  + ry*4*97;
    const float* M   = sM  + ry*4*97;
    const float* Wsp = sWs + cx*3*97;
    const float* Wdp = sWd + cx*3*97;
    const float* W0p = sW0 + cx*3*97;
    float aX[12], aS[12];
    #pragma unroll
    for (int i=0;i<12;i++){ aX[i]=0.f; aS[i]=0.f; }
    #pragma unroll 2
    for (int k=0;k<96;k++){
      float xv[4], mv[4];
      #pragma unroll
      for (int j=0;j<4;j++){ xv[j]=A[j*97+k]; mv[j]=M[j*97+k]; }
      #pragma unroll
      for (int i=0;i<3;i++){
        float fws=Wsp[i*97+k], fwd=Wdp[i*97+k], fw0=W0p[i*97+k];
        #pragma unroll
        for (int j=0;j<4;j++){
          aX[j*3+i] = fmaf(xv[j], fws, fmaf(mv[j], fwd, aX[j*3+i]));
          aS[j*3+i] = fmaf(xv[j], fw0, aS[j*3+i]);
        }
      }
    }
    #pragma unroll
    for (int j=0;j<4;j++){
      size_t row = row0 + ry*4 + j;
      #pragma unroll
      for (int i=0;i<3;i++){
        int c = c0 + cx*3 + i;
        size_t g = row*96 + c;
        g_xx[g]    = aX[j*3+i] + bs[c] + bt[c];
        g_skipA[g] = aS[j*3+i] + b0[c];
      }
    }
  }
}

// ---------------- k_m2: topk (blocks 0..2047) | xg (blocks 2048..3071) ----
__global__ void __launch_bounds__(256) k_m2(
    const float* __restrict__ l1w, const float* __restrict__ l1b,
    const float* __restrict__ s1w, const float* __restrict__ s1b,
    const float* __restrict__ msgw, const float* __restrict__ msgb,
    const float* __restrict__ gatew, const float* __restrict__ gateb){
  extern __shared__ float sm[];
  __shared__ unsigned long long red[8];
  __shared__ unsigned long long s_win;
  __shared__ float sMW[2*DG*DH];
  const int bx = blockIdx.x;
  const int tid = threadIdx.x;
  if (bx < 2048){
    // ---- top-k + degree count ----
    const int row = bx;
    const float* ar = g_adj + (size_t)row*NNODE;
    unsigned long long key[8];
    #pragma unroll
    for (int j=0;j<8;j++){
      int i = j*256 + tid;
      unsigned int b = __float_as_uint(ar[i]);
      b = (b & 0x80000000u) ? ~b : (b | 0x80000000u);
      key[j] = ((unsigned long long)b<<32) | (unsigned int)(NNODE-1-i);
    }
    for (int k=0;k<KE;k++){
      unsigned long long best = key[0];
      #pragma unroll
      for (int j=1;j<8;j++) best = best > key[j] ? best : key[j];
      #pragma unroll
      for (int o=16;o;o>>=1){
        unsigned long long other = __shfl_xor_sync(0xffffffffu, best, o);
        if (other > best) best = other;
      }
      if ((tid&31)==0) red[tid>>5] = best;
      __syncthreads();
      if (tid==0){
        unsigned long long bb = red[0];
        #pragma unroll
        for (int i=1;i<8;i++) if (red[i] > bb) bb = red[i];
        s_win = bb;
        int idx = NNODE-1-(int)(bb & 0xffffffffull);
        bool pos = ((unsigned int)(bb>>32) > 0x80000000u);
        g_cols[row*KE+k]  = idx;
        g_maskv[row*KE+k] = pos ? 1.f : 0.f;
        if (pos) atomicAdd(&g_cnt[idx], 1);
      }
      __syncthreads();
      int idx = NNODE-1-(int)(s_win & 0xffffffffull);
      if ((idx & 255) == tid) key[idx>>8] = 0ull;
    }
  } else {
    // ---- xg: gemm + s1 + h/gate ----
    float* sA = sm;
    float* sW = sA + 64*97;
    const size_t row0 = (size_t)(bx - 2048)*64;
    for (int i=tid;i<64*96;i+=256){
      int r=i/96, c=i-r*96;
      sA[r*97+c] = g_xx[(row0+r)*96 + c];
      sW[r*97+c] = l1w[i];
    }
    for (int i=tid;i<DG*DH;i+=256){
      sMW[i] = msgw[i];
      sMW[DG*DH + i] = gatew[i];
    }
    __syncthreads();
    const int cx = tid & 15, ry = tid >> 4;
    {
      const float* A = sA + ry*4*97;
      const float* W = sW + cx*4*97;
      float acc[16];
      #pragma unroll
      for (int i=0;i<16;i++) acc[i]=0.f;
      #pragma unroll 2
      for (int k=0;k<96;k++){
        float a[4];
        #pragma unroll
        for (int j=0;j<4;j++) a[j]=A[j*97+k];
        #pragma unroll
        for (int i=0;i<4;i++){
          float w = W[i*97+k];
          #pragma unroll
          for (int j=0;j<4;j++) acc[j*4+i] = fmaf(a[j], w, acc[j*4+i]);
        }
      }
      if (tid < 64){
        float s = 0.f;
        #pragma unroll 4
        for (int k=0;k<96;k++) s = fmaf(sA[tid*97+k], s1w[k], s);
        g_s1[row0+tid] = s + s1b[0];
      }
      __syncthreads();
      #pragma unroll
      for (int j=0;j<4;j++)
        #pragma unroll
        for (int i=0;i<4;i++)
          sW[(ry*4+j)*65 + cx*4+i] = acc[j*4+i] + l1b[cx*4+i];
    }
    __syncthreads();
    const int row = tid >> 2, q = tid & 3;
    float ha[4] = {0,0,0,0}, ga[4] = {0,0,0,0};
    #pragma unroll 4
    for (int k=0;k<DH;k++){
      float xv = sW[row*65+k];
      #pragma unroll
      for (int i=0;i<4;i++){
        ha[i] = fmaf(xv, sMW[(q*4+i)*DH+k], ha[i]);
        ga[i] = fmaf(xv, sMW[DG*DH + (q*4+i)*DH+k], ga[i]);
      }
    }
    size_t r = row0 + row;
    #pragma unroll
    for (int i=0;i<4;i++){
      int d = q*4+i;
      g_h[r*DG+d]    = ha[i] + msgb[d];
      g_gate[r*DG+d] = 1.f/(1.f+expf(-(ga[i]+gateb[d])));
    }
  }
}

// ---------------- scan: 1 block over 2048 counts ----
__global__ void k_scan(){
  __shared__ int sa[NNODE], sb[NNODE];
  const int t = threadIdx.x;    // 1024
  sa[t] = g_cnt[t]; sa[t+1024] = g_cnt[t+1024];
  __syncthreads();
  int *src=sa, *dst=sb;
  for (int off=1; off<NNODE; off<<=1){
    for (int i=t;i<NNODE;i+=1024){
      int v = src[i];
      if (i >= off) v += src[i-off];
      dst[i] = v;
    }
    __syncthreads();
    int* tmp=src; src=dst; dst=tmp;
  }
  if (t==0) g_ptr[0]=0;
  g_ptr[t+1] = src[t];
  g_ptr[t+1024+1] = src[t+1024];
}

// ---------------- fill: parallel ----
__global__ void k_fill(){
  int idx = blockIdx.x*256+threadIdx.x;
  if (idx >= NNODE*KE) return;
  if (g_maskv[idx] > 0.f){
    int n = idx/KE;
    int c = g_cols[idx];
    int s = atomicAdd(&g_cnt2[c], 1);
    g_rsrc[g_ptr[c]+s] = n;
  }
}

// ---------------- gated aggregation ----
__global__ void k_agg(){
  int b = blockIdx.y;
  int n = blockIdx.x*16 + (threadIdx.x>>4);
  int d = threadIdx.x & 15;
  const float* hb = g_h + (size_t)b*NNODE*DG;
  float acc = 0.f;
  int base = n*KE;
  #pragma unroll
  for (int k=0;k<KE;k++){
    if (g_maskv[base+k] > 0.f) acc += hb[(size_t)g_cols[base+k]*DG + d];
  }
  int e0 = g_ptr[n], e1 = g_ptr[n+1];
  for (int e=e0; e<e1; e++) acc += hb[(size_t)g_rsrc[e]*DG + d];
  size_t idx = ((size_t)b*NNODE + n)*DG + d;
  g_xgg[idx] = g_gate[idx]*acc;
}

// ---------------- xx2 = xgg@lin2^T+b+residual; partial stats ----
__global__ void __launch_bounds__(256) k_gemm_lin2(
    const float* __restrict__ l2w, const float* __restrict__ l2b,
    const float* __restrict__ xin){
  __shared__ float sA[64*17];
  __shared__ float sW[96*17];
  __shared__ float rb[16];
  const int tid = threadIdx.x;
  const size_t row0 = (size_t)blockIdx.x*64;
  for (int i=tid;i<64*16;i+=256)
    sA[(i>>4)*17 + (i&15)] = g_xgg[row0*DG + i];
  for (int i=tid;i<96*16;i+=256)
    sW[(i>>4)*17 + (i&15)] = l2w[i];
  __syncthreads();
  const int cx = tid & 15, ry = tid >> 4;
  float acc[24];
  #pragma unroll
  for (int i=0;i<24;i++) acc[i]=0.f;
  #pragma unroll
  for (int k=0;k<16;k++){
    float a[4];
    #pragma unroll
    for (int j=0;j<4;j++) a[j]=sA[(ry*4+j)*17+k];
    #pragma unroll
    for (int i=0;i<6;i++){
      float w = sW[(cx*6+i)*17+k];
      #pragma unroll
      for (int j=0;j<4;j++) acc[j*6+i] = fmaf(a[j], w, acc[j*6+i]);
    }
  }
  float ls=0.f, ls2=0.f;
  #pragma unroll
  for (int j=0;j<4;j++){
    size_t row = row0 + ry*4 + j;
    #pragma unroll
    for (int i=0;i<6;i++){
      int c = cx*6 + i;
      size_t g = row*96 + c;
      float v = acc[j*6+i] + l2b[c] + xin[g];
      g_xx2[g] = v;
      ls += v; ls2 = fmaf(v, v, ls2);
    }
  }
  #pragma unroll
  for (int o=16;o;o>>=1){
    ls  += __shfl_xor_sync(0xffffffffu, ls,  o);
    ls2 += __shfl_xor_sync(0xffffffffu, ls2, o);
  }
  int warp = tid>>5, lane = tid&31;
  if (lane==0){ rb[warp]=ls; rb[8+warp]=ls2; }
  __syncthreads();
  if (tid==0){
    float s=0.f, s2=0.f;
    #pragma unroll
    for (int i=0;i<8;i++){ s+=rb[i]; s2+=rb[8+i]; }
    g_part[blockIdx.x*2]   = s;
    g_part[blockIdx.x*2+1] = s2;
  }
}

__global__ void k_stats(){
  int t = threadIdx.x;
  int b = t >> 5, j = t & 31;
  float s  = g_part[(b*32+j)*2];
  float s2 = g_part[(b*32+j)*2+1];
  #pragma unroll
  for (int o=16;o;o>>=1){
    s  += __shfl_xor_sync(0xffffffffu, s,  o);
    s2 += __shfl_xor_sync(0xffffffffu, s2, o);
  }
  if (j==0){
    const float inv = 1.f/(float)((size_t)NNODE*TT);
    float mu = s*inv;
    float var = s2*inv - mu*mu;
    g_mu[b] = mu;
    g_rstd[b] = rsqrtf(var + 1e-5f);
  }
}

// ---------------- k_tail: LN -> e1 GEMM + skip + relu (smem) -> l3/l4 head -> out ----
__global__ void __launch_bounds__(256) k_tail(
    const float* __restrict__ e1w, const float* __restrict__ e1b,
    const float* __restrict__ lnw, const float* __restrict__ lnb,
    const float* __restrict__ l3w, const float* __restrict__ l3b,
    const float* __restrict__ l4w, const float* __restrict__ l4b,
    float* __restrict__ out){
  extern __shared__ float sm[];
  float* sA = sm;            // 64*97
  float* sW = sA + 64*97;    // 96*97
  const int tid = threadIdx.x;
  const size_t row0 = (size_t)blockIdx.x*64;
  const int b = (int)(row0 >> 11);
  const float mu = g_mu[b], rstd = g_rstd[b];
  for (int i=tid;i<64*96;i+=256){
    int r=i/96, c=i-r*96;
    size_t row = row0+r; int n = (int)(row & (NNODE-1));
    float v = g_xx2[row*96+c];
    sA[r*97+c] = fmaf((v-mu)*rstd, lnw[n*96+c], lnb[n*96+c]);
  }
  for (int i=tid;i<96*96;i+=256){
    int r=i/96, c=i-r*96;
    sW[r*97+c] = e1w[i];
  }
  __syncthreads();
  const int cx = tid & 15, ry = tid >> 4;
  float acc[24];
  {
    const float* A = sA + ry*4*97;
    const float* W = sW + cx*6*97;
    #pragma unroll
    for (int i=0;i<24;i++) acc[i]=0.f;
    #pragma unroll 2
    for (int k=0;k<96;k++){
      float a[4];
      #pragma unroll
      for (int j=0;j<4;j++) a[j]=A[j*97+k];
      #pragma unroll
      for (int i=0;i<6;i++){
        float w = W[i*97+k];
        #pragma unroll
        for (int j=0;j<4;j++) acc[j*6+i] = fmaf(a[j], w, acc[j*6+i]);
      }
    }
  }
  __syncthreads();
  #pragma unroll
  for (int j=0;j<4;j++){
    size_t row = row0 + ry*4 + j;
    float s1v = g_s1[row];
    #pragma unroll
    for (int i=0;i<6;i++){
      int c = cx*6 + i;
      float v = acc[j*6+i] + e1b[c] + g_skipA[row*96+c] + s1v;
      sA[(ry*4+j)*97 + c] = fmaxf(v, 0.f);
    }
  }
  for (int i=tid;i<64*96;i+=256){
    int r=i/96, c=i-r*96;
    sW[r*97+c] = l3w[i];
  }
  __syncthreads();
  float acc2[16];
  {
    const float* A = sA + ry*4*97;
    const float* W = sW + cx*4*97;
    #pragma unroll
    for (int i=0;i<16;i++) acc2[i]=0.f;
    #pragma unroll 2
    for (int k=0;k<96;k++){
      float a[4];
      #pragma unroll
      for (int j=0;j<4;j++) a[j]=A[j*97+k];
      #pragma unroll
      for (int i=0;i<4;i++){
        float w = W[i*97+k];
        #pragma unroll
        for (int j=0;j<4;j++) acc2[j*4+i] = fmaf(a[j], w, acc2[j*4+i]);
      }
    }
  }
  float part[4];
  #pragma unroll
  for (int j=0;j<4;j++){
    float s = 0.f;
    #pragma unroll
    for (int i=0;i<4;i++){
      int c = cx*4 + i;
      float y = fmaxf(acc2[j*4+i] + l3b[c], 0.f);
      s = fmaf(y, l4w[c], s);
    }
    part[j] = s;
  }
  #pragma unroll
  for (int j=0;j<4;j++){
    #pragma unroll
    for (int o=8;o;o>>=1) part[j] += __shfl_xor_sync(0xffffffffu, part[j], o);
  }
  if (cx==0){
    #pragma unroll
    for (int j=0;j<4;j++)
      out[row0 + ry*4 + j] = part[j] + l4b[0];
  }
}

extern "C" void kernel_launch(void* const* d_in, const int* in_sizes, int n_in,
                              void* d_out, int out_size) {
  const float* x    = (const float*)d_in[0];
  const float* emb1 = (const float*)d_in[1];
  const float* emb2 = (const float*)d_in[2];
  const float* gc_w1= (const float*)d_in[3];
  const float* gc_b1= (const float*)d_in[4];
  const float* gc_w2= (const float*)d_in[5];
  const float* gc_b2= (const float*)d_in[6];
  const float* sk0w = (const float*)d_in[7];
  const float* sk0b = (const float*)d_in[8];
  const float* sk1w = (const float*)d_in[9];
  const float* sk1b = (const float*)d_in[10];
  const float* e1w  = (const float*)d_in[11];
  const float* e1b  = (const float*)d_in[12];
  const float* lsw  = (const float*)d_in[13];
  const float* lsb  = (const float*)d_in[14];
  const float* ltw  = (const float*)d_in[15];
  const float* ltb  = (const float*)d_in[16];
  const float* l1w  = (const float*)d_in[17];
  const float* l1b  = (const float*)d_in[18];
  const float* l2w  = (const float*)d_in[19];
  const float* l2b  = (const float*)d_in[20];
  const float* l3w  = (const float*)d_in[21];
  const float* l3b  = (const float*)d_in[22];
  const float* l4w  = (const float*)d_in[23];
  const float* l4b  = (const float*)d_in[24];
  const float* msgw = (const float*)d_in[25];
  const float* msgb = (const float*)d_in[26];
  const float* gatew= (const float*)d_in[27];
  const float* gateb= (const float*)d_in[28];
  const float* lnw  = (const float*)d_in[29];
  const float* lnb  = (const float*)d_in[30];
  float* out = (float*)d_out;

  const int SM1  = (64*97*2 + 48*97*3)*4;  // k_m1: 105.5KB
  const int SM2  = (64*97*2)*4;            // k_m2: 49.7KB
  const int SMT  = (64*97 + 96*97)*4;      // k_tail: 62.1KB
  cudaFuncSetAttribute(k_m1,   cudaFuncAttributeMaxDynamicSharedMemorySize, SM1);
  cudaFuncSetAttribute(k_m2,   cudaFuncAttributeMaxDynamicSharedMemorySize, SM2);
  cudaFuncSetAttribute(k_tail, cudaFuncAttributeMaxDynamicSharedMemorySize, SMT);

  k_graphpre<<<684, 256>>>(emb1, emb2, gc_w1, gc_b1, gc_w2, gc_b2, ltw, lsw);
  k_m1<<<1024 + 2048, 256, SM1>>>(x, sk0w, sk0b, lsw, lsb, ltb);
  k_m2<<<2048 + 1024, 256, SM2>>>(l1w, l1b, sk1w, sk1b, msgw, msgb, gatew, gateb);
  k_scan<<<1, 1024>>>();
  k_fill<<<(NNODE*KE+255)/256, 256>>>();
  k_agg<<<dim3(NNODE/16, NB), 256>>>();
  k_gemm_lin2<<<NROWS/64, 256>>>(l2w, l2b, x);
  k_stats<<<1, 1024>>>();
  k_tail<<<NROWS/64, 256, SMT>>>(e1w, e1b, lnw, lnb, l3w, l3b, l4w, l4b, out);
}